// round 2
// baseline (speedup 1.0000x reference)
#include <cuda_runtime.h>

#define SEQ 1600
#define BH 64            /* batch(8) * heads(8) */
#define HD 64
#define OUT_ELEMS (8*SEQ*512)

__device__ float g_q[(size_t)BH*SEQ*HD];
__device__ float g_k[(size_t)BH*SEQ*HD];
__device__ float g_v[(size_t)BH*SEQ*HD];
__device__ float g_partial[(size_t)BH*SEQ*25];
__device__ float g_rowinv[(size_t)BH*SEQ];

typedef unsigned long long ull;
__device__ __forceinline__ ull pk2(float a, float b) {
    ull r; asm("mov.b64 %0, {%1, %2};" : "=l"(r) : "f"(a), "f"(b)); return r;
}
__device__ __forceinline__ float2 upk2(ull v) {
    float2 f; asm("mov.b64 {%0, %1}, %2;" : "=f"(f.x), "=f"(f.y) : "l"(v)); return f;
}
__device__ __forceinline__ ull fma2(ull a, ull b, ull c) {
    ull d; asm("fma.rn.f32x2 %0, %1, %2, %3;" : "=l"(d) : "l"(a), "l"(b), "l"(c)); return d;
}

// ================= K1: QKV projection =================
// C[12800x512] = X[12800x256] @ W[256x512] + bias ; z selects Q(scale 1/8)/K/V(relu)
__global__ __launch_bounds__(256) void proj_kernel(
    const float* __restrict__ x,
    const float* __restrict__ wq, const float* __restrict__ bq,
    const float* __restrict__ wk, const float* __restrict__ bk,
    const float* __restrict__ wv, const float* __restrict__ bv)
{
    __shared__ __align__(16) float As[16*68];  // [k][m] transposed, pad 68
    __shared__ __align__(16) float Bs[16*64];  // [k][n]
    int tid = threadIdx.x, tx = tid & 15, ty = tid >> 4;
    int m0 = blockIdx.x * 64, n0 = blockIdx.y * 64, mat = blockIdx.z;
    const float* w  = (mat == 0) ? wq : ((mat == 1) ? wk : wv);
    const float* bb = (mat == 0) ? bq : ((mat == 1) ? bk : bv);
    float* dst      = (mat == 0) ? g_q : ((mat == 1) ? g_k : g_v);

    ull acc[4][2];
    #pragma unroll
    for (int i = 0; i < 4; i++) { acc[i][0] = 0ULL; acc[i][1] = 0ULL; }

    for (int kc = 0; kc < 256; kc += 16) {
        {
            int r = tid >> 2, c4 = tid & 3;
            float4 v = *(const float4*)&x[(size_t)(m0 + r) * 256 + kc + c4 * 4];
            As[(c4*4+0)*68 + r] = v.x;
            As[(c4*4+1)*68 + r] = v.y;
            As[(c4*4+2)*68 + r] = v.z;
            As[(c4*4+3)*68 + r] = v.w;
        }
        {
            int r = tid >> 4, c = tid & 15;
            *(float4*)&Bs[r*64 + c*4] = *(const float4*)&w[(size_t)(kc + r)*512 + n0 + c*4];
        }
        __syncthreads();
        #pragma unroll
        for (int kk = 0; kk < 16; kk++) {
            float4 a4 = *(const float4*)&As[kk*68 + ty*4];
            ulonglong2 b2 = *(const ulonglong2*)&Bs[kk*64 + tx*4];
            ull a0 = pk2(a4.x, a4.x), a1 = pk2(a4.y, a4.y);
            ull a2 = pk2(a4.z, a4.z), a3 = pk2(a4.w, a4.w);
            acc[0][0] = fma2(a0, b2.x, acc[0][0]); acc[0][1] = fma2(a0, b2.y, acc[0][1]);
            acc[1][0] = fma2(a1, b2.x, acc[1][0]); acc[1][1] = fma2(a1, b2.y, acc[1][1]);
            acc[2][0] = fma2(a2, b2.x, acc[2][0]); acc[2][1] = fma2(a2, b2.y, acc[2][1]);
            acc[3][0] = fma2(a3, b2.x, acc[3][0]); acc[3][1] = fma2(a3, b2.y, acc[3][1]);
        }
        __syncthreads();
    }

    float4 bias4 = *(const float4*)&bb[n0 + tx*4];
    int h = n0 >> 6;
    #pragma unroll
    for (int i = 0; i < 4; i++) {
        int m = m0 + ty*4 + i;
        int bI = m / SEQ, sI = m % SEQ;
        float2 lo = upk2(acc[i][0]), hi = upk2(acc[i][1]);
        float4 v = make_float4(lo.x + bias4.x, lo.y + bias4.y, hi.x + bias4.z, hi.y + bias4.w);
        if (mat == 0) { v.x *= 0.125f; v.y *= 0.125f; v.z *= 0.125f; v.w *= 0.125f; }
        if (mat == 2) {
            v.x = fmaxf(v.x, 0.f); v.y = fmaxf(v.y, 0.f);
            v.z = fmaxf(v.z, 0.f); v.w = fmaxf(v.w, 0.f);
        }
        *(float4*)&dst[(((size_t)(bI*8 + h))*SEQ + sI)*HD + tx*4] = v;
    }
}

// ================= K2: scores -> masked exp -> p region + partial row sums =================
__global__ __launch_bounds__(256) void score_kernel(float* __restrict__ p)
{
    __shared__ __align__(16) float QsT[64*68];  // [d][q]
    __shared__ __align__(16) float KsT[64*68];  // [d][k]
    int tid = threadIdx.x, tx = tid & 15, ty = tid >> 4;
    int kt = blockIdx.x, qt = blockIdx.y, bh = blockIdx.z;

    const float* Qg = g_q + ((size_t)bh*SEQ + qt*64)*HD;
    const float* Kg = g_k + ((size_t)bh*SEQ + kt*64)*HD;

    #pragma unroll
    for (int it = 0; it < 4; it++) {
        int row = it*16 + (tid >> 4), c4 = tid & 15;
        float4 q4 = *(const float4*)&Qg[row*64 + c4*4];
        QsT[(c4*4+0)*68 + row] = q4.x; QsT[(c4*4+1)*68 + row] = q4.y;
        QsT[(c4*4+2)*68 + row] = q4.z; QsT[(c4*4+3)*68 + row] = q4.w;
        float4 k4 = *(const float4*)&Kg[row*64 + c4*4];
        KsT[(c4*4+0)*68 + row] = k4.x; KsT[(c4*4+1)*68 + row] = k4.y;
        KsT[(c4*4+2)*68 + row] = k4.z; KsT[(c4*4+3)*68 + row] = k4.w;
    }
    __syncthreads();

    ull acc[4][2];
    #pragma unroll
    for (int i = 0; i < 4; i++) { acc[i][0] = 0ULL; acc[i][1] = 0ULL; }

    #pragma unroll 16
    for (int d = 0; d < 64; d++) {
        float4 a4 = *(const float4*)&QsT[d*68 + ty*4];
        ulonglong2 b2 = *(const ulonglong2*)&KsT[d*68 + tx*4];
        ull a0 = pk2(a4.x, a4.x), a1 = pk2(a4.y, a4.y);
        ull a2 = pk2(a4.z, a4.z), a3 = pk2(a4.w, a4.w);
        acc[0][0] = fma2(a0, b2.x, acc[0][0]); acc[0][1] = fma2(a0, b2.y, acc[0][1]);
        acc[1][0] = fma2(a1, b2.x, acc[1][0]); acc[1][1] = fma2(a1, b2.y, acc[1][1]);
        acc[2][0] = fma2(a2, b2.x, acc[2][0]); acc[2][1] = fma2(a2, b2.y, acc[2][1]);
        acc[3][0] = fma2(a3, b2.x, acc[3][0]); acc[3][1] = fma2(a3, b2.y, acc[3][1]);
    }

    int k0 = kt*64 + tx*4;
    int kf0 = (k0    ) / 25, kf1 = (k0 + 1) / 25, kf2 = (k0 + 2) / 25, kf3 = (k0 + 3) / 25;
    #pragma unroll
    for (int i = 0; i < 4; i++) {
        int qi = qt*64 + ty*4 + i;
        int qf = qi / 25;
        float2 lo = upk2(acc[i][0]), hi = upk2(acc[i][1]);
        float4 e;
        e.x = (qf != kf0 || qi == k0    ) ? __expf(lo.x) : 0.f;
        e.y = (qf != kf1 || qi == k0 + 1) ? __expf(lo.y) : 0.f;
        e.z = (qf != kf2 || qi == k0 + 2) ? __expf(hi.x) : 0.f;
        e.w = (qf != kf3 || qi == k0 + 3) ? __expf(hi.y) : 0.f;
        *(float4*)&p[((size_t)bh*SEQ + qi)*SEQ + k0] = e;

        float r = e.x + e.y + e.z + e.w;
        r += __shfl_down_sync(0xffffffffu, r, 8, 16);
        r += __shfl_down_sync(0xffffffffu, r, 4, 16);
        r += __shfl_down_sync(0xffffffffu, r, 2, 16);
        r += __shfl_down_sync(0xffffffffu, r, 1, 16);
        if (tx == 0) g_partial[((size_t)bh*SEQ + qi)*25 + kt] = r;
    }
}

// ================= K3: row inverse =================
__global__ __launch_bounds__(256) void rowinv_kernel()
{
    int row = blockIdx.x * 256 + threadIdx.x;
    if (row >= BH*SEQ) return;
    float s = 0.f;
    #pragma unroll
    for (int t = 0; t < 25; t++) s += g_partial[(size_t)row*25 + t];
    g_rowinv[row] = 1.0f / s;
}

// ================= K4: normalize p in place + out = P @ V =================
__global__ __launch_bounds__(256) void pv_kernel(float* __restrict__ p, float* __restrict__ out)
{
    __shared__ __align__(16) float EsT[64*68];  // [k][q]
    __shared__ __align__(16) float Vs[64*64];   // [k][d]
    __shared__ float rs[64];
    int tid = threadIdx.x, tx = tid & 15, ty = tid >> 4;
    int qt = blockIdx.x, bh = blockIdx.y;

    if (tid < 64) rs[tid] = g_rowinv[(size_t)bh*SEQ + qt*64 + tid];
    __syncthreads();

    ull acc[4][2];
    #pragma unroll
    for (int i = 0; i < 4; i++) { acc[i][0] = 0ULL; acc[i][1] = 0ULL; }

    const float* Vg = g_v + (size_t)bh*SEQ*HD;

    for (int kt = 0; kt < 25; kt++) {
        #pragma unroll
        for (int it = 0; it < 4; it++) {
            int q = it*16 + (tid >> 4), c4 = tid & 15;
            float* paddr = p + ((size_t)bh*SEQ + qt*64 + q)*SEQ + kt*64 + c4*4;
            float4 e4 = *(float4*)paddr;
            float rv = rs[q];
            e4.x *= rv; e4.y *= rv; e4.z *= rv; e4.w *= rv;
            *(float4*)paddr = e4;
            EsT[(c4*4+0)*68 + q] = e4.x; EsT[(c4*4+1)*68 + q] = e4.y;
            EsT[(c4*4+2)*68 + q] = e4.z; EsT[(c4*4+3)*68 + q] = e4.w;

            int r = it*16 + (tid >> 4);
            *(float4*)&Vs[r*64 + c4*4] = *(const float4*)&Vg[(size_t)(kt*64 + r)*64 + c4*4];
        }
        __syncthreads();
        #pragma unroll 16
        for (int kk = 0; kk < 64; kk++) {
            float4 a4 = *(const float4*)&EsT[kk*68 + ty*4];
            ulonglong2 b2 = *(const ulonglong2*)&Vs[kk*64 + tx*4];
            ull a0 = pk2(a4.x, a4.x), a1 = pk2(a4.y, a4.y);
            ull a2 = pk2(a4.z, a4.z), a3 = pk2(a4.w, a4.w);
            acc[0][0] = fma2(a0, b2.x, acc[0][0]); acc[0][1] = fma2(a0, b2.y, acc[0][1]);
            acc[1][0] = fma2(a1, b2.x, acc[1][0]); acc[1][1] = fma2(a1, b2.y, acc[1][1]);
            acc[2][0] = fma2(a2, b2.x, acc[2][0]); acc[2][1] = fma2(a2, b2.y, acc[2][1]);
            acc[3][0] = fma2(a3, b2.x, acc[3][0]); acc[3][1] = fma2(a3, b2.y, acc[3][1]);
        }
        __syncthreads();
    }

    int b = bh >> 3, h = bh & 7;
    #pragma unroll
    for (int i = 0; i < 4; i++) {
        int s = qt*64 + ty*4 + i;
        float2 lo = upk2(acc[i][0]), hi = upk2(acc[i][1]);
        float4 v = make_float4(lo.x, lo.y, hi.x, hi.y);
        *(float4*)&out[((size_t)(b*SEQ + s))*512 + h*64 + tx*4] = v;
    }
}

extern "C" void kernel_launch(void* const* d_in, const int* in_sizes, int n_in,
                              void* d_out, int out_size)
{
    const float* x  = (const float*)d_in[0];
    const float* wq = (const float*)d_in[1];
    const float* bq = (const float*)d_in[2];
    const float* wk = (const float*)d_in[3];
    const float* bk = (const float*)d_in[4];
    const float* wv = (const float*)d_in[5];
    const float* bv = (const float*)d_in[6];
    float* out = (float*)d_out;
    float* p   = out + OUT_ELEMS;

    proj_kernel<<<dim3(200, 8, 3), 256>>>(x, wq, bq, wk, bk, wv, bv);
    score_kernel<<<dim3(25, 25, BH), 256>>>(p);
    rowinv_kernel<<<dim3((BH*SEQ + 255)/256), 256>>>();
    pv_kernel<<<dim3(25, BH), 256>>>(p, out);
}

// round 3
// speedup vs baseline: 1.0046x; 1.0046x over previous
#include <cuda_runtime.h>

#define SEQ 1600
#define BH 64
#define OUT_ELEMS (8*SEQ*512)

__device__ float g_q[(size_t)BH*64*SEQ];   // [bh][d][s]  (pre-transposed)
__device__ float g_k[(size_t)BH*64*SEQ];   // [bh][d][s]
__device__ float g_v[(size_t)BH*SEQ*64];   // [bh][s][d]
__device__ float g_partial[(size_t)BH*SEQ*25];
__device__ float g_rowinv[(size_t)BH*SEQ];

typedef unsigned long long ull;
__device__ __forceinline__ ull pk2(float a, float b) {
    ull r; asm("mov.b64 %0, {%1, %2};" : "=l"(r) : "f"(a), "f"(b)); return r;
}
__device__ __forceinline__ float2 upk2(ull v) {
    float2 f; asm("mov.b64 {%0, %1}, %2;" : "=f"(f.x), "=f"(f.y) : "l"(v)); return f;
}
__device__ __forceinline__ ull fma2(ull a, ull b, ull c) {
    ull d; asm("fma.rn.f32x2 %0, %1, %2, %3;" : "=l"(d) : "l"(a), "l"(b), "l"(c)); return d;
}

// 8x8 micro-tile step: a from As_row[ty*8..+8], b from Bs_row[tx*8..+8]
#define MAINSTEP(As_row, Bs_row) do {                                   \
    const float4 a0 = *(const float4*)((As_row) + ty*8);                \
    const float4 a1 = *(const float4*)((As_row) + ty*8 + 4);            \
    const ulonglong2 b0 = *(const ulonglong2*)((Bs_row) + tx*8);        \
    const ulonglong2 b1 = *(const ulonglong2*)((Bs_row) + tx*8 + 4);    \
    const float av[8] = {a0.x,a0.y,a0.z,a0.w,a1.x,a1.y,a1.z,a1.w};      \
    _Pragma("unroll")                                                   \
    for (int _i = 0; _i < 8; _i++) {                                    \
        const ull aa = pk2(av[_i], av[_i]);                             \
        acc[_i][0] = fma2(aa, b0.x, acc[_i][0]);                        \
        acc[_i][1] = fma2(aa, b0.y, acc[_i][1]);                        \
        acc[_i][2] = fma2(aa, b1.x, acc[_i][2]);                        \
        acc[_i][3] = fma2(aa, b1.y, acc[_i][3]);                        \
    } } while (0)

// ================= K1: QKV projection =================
// C[12800x512] = X @ W + b.  Q scaled 1/8 and stored [bh][d][s];
// K stored [bh][d][s]; V relu'd, stored [bh][s][d].
__global__ __launch_bounds__(64) void proj_kernel(
    const float* __restrict__ x,
    const float* __restrict__ wq, const float* __restrict__ bq,
    const float* __restrict__ wk, const float* __restrict__ bk,
    const float* __restrict__ wv, const float* __restrict__ bv)
{
    __shared__ __align__(16) float As[16*68];
    __shared__ __align__(16) float Bs[16*68];
    const int tid = threadIdx.x, tx = tid & 7, ty = tid >> 3;
    const int m0 = blockIdx.x*64, n0 = blockIdx.y*64, mat = blockIdx.z;
    const float* w  = (mat==0) ? wq : ((mat==1) ? wk : wv);
    const float* bb = (mat==0) ? bq : ((mat==1) ? bk : bv);

    ull acc[8][4];
    #pragma unroll
    for (int i = 0; i < 8; i++)
        #pragma unroll
        for (int j = 0; j < 4; j++) acc[i][j] = 0ULL;

    for (int kc = 0; kc < 256; kc += 16) {
        // X chunk 64(m) x 16(k) -> As[k][m] transposed
        float4 xv[4];
        #pragma unroll
        for (int j = 0; j < 4; j++)
            xv[j] = *(const float4*)&x[(size_t)(m0 + tid)*256 + kc + j*4];
        #pragma unroll
        for (int j = 0; j < 4; j++) {
            As[(j*4+0)*68 + tid] = xv[j].x;
            As[(j*4+1)*68 + tid] = xv[j].y;
            As[(j*4+2)*68 + tid] = xv[j].z;
            As[(j*4+3)*68 + tid] = xv[j].w;
        }
        // W chunk 16(k) x 64(n) natural
        {
            const int r = tid >> 2, fb = (tid & 3) * 4;
            #pragma unroll
            for (int j = 0; j < 4; j++)
                *(float4*)&Bs[r*68 + (fb+j)*4] =
                    *(const float4*)&w[(size_t)(kc + r)*512 + n0 + (fb+j)*4];
        }
        __syncthreads();
        #pragma unroll
        for (int kk = 0; kk < 16; kk++) MAINSTEP(&As[kk*68], &Bs[kk*68]);
        __syncthreads();
    }

    float b8[8];
    #pragma unroll
    for (int j = 0; j < 8; j++) b8[j] = bb[n0 + tx*8 + j];
    const int bI = m0 / SEQ;
    const int s0 = (m0 % SEQ) + ty*8;
    const int h  = n0 >> 6, bh = bI*8 + h;
    const int d0 = (n0 & 63) + tx*8;

    float o[8][8];
    #pragma unroll
    for (int i = 0; i < 8; i++) {
        #pragma unroll
        for (int j = 0; j < 4; j++) {
            float2 t = upk2(acc[i][j]);
            o[i][j*2]   = t.x + b8[j*2];
            o[i][j*2+1] = t.y + b8[j*2+1];
        }
        if (mat == 0) {
            #pragma unroll
            for (int j = 0; j < 8; j++) o[i][j] *= 0.125f;
        }
        if (mat == 2) {
            #pragma unroll
            for (int j = 0; j < 8; j++) o[i][j] = fmaxf(o[i][j], 0.f);
        }
    }

    if (mat == 2) {
        #pragma unroll
        for (int i = 0; i < 8; i++) {
            float* dr = &g_v[((size_t)bh*SEQ + s0 + i)*64 + d0];
            *(float4*)dr       = make_float4(o[i][0], o[i][1], o[i][2], o[i][3]);
            *(float4*)(dr + 4) = make_float4(o[i][4], o[i][5], o[i][6], o[i][7]);
        }
    } else {
        float* dst = (mat == 0) ? g_q : g_k;
        #pragma unroll
        for (int j = 0; j < 8; j++) {
            float* dr = &dst[((size_t)bh*64 + d0 + j)*SEQ + s0];
            *(float4*)dr       = make_float4(o[0][j], o[1][j], o[2][j], o[3][j]);
            *(float4*)(dr + 4) = make_float4(o[4][j], o[5][j], o[6][j], o[7][j]);
        }
    }
}

// ================= K2: scores -> masked exp -> p + partial row sums =================
__global__ __launch_bounds__(64) void score_kernel(float* __restrict__ p)
{
    __shared__ __align__(16) float Qs[64*68];   // [d][q]
    __shared__ __align__(16) float Ks[64*68];   // [d][k]
    const int tid = threadIdx.x, tx = tid & 7, ty = tid >> 3;
    const int kt = blockIdx.x, qt = blockIdx.y, bh = blockIdx.z;
    const float* Qg = g_q + (size_t)bh*64*SEQ;
    const float* Kg = g_k + (size_t)bh*64*SEQ;
    const int f = tid & 15, dr = tid >> 4;

    #pragma unroll
    for (int j = 0; j < 16; j++) {
        const int d = dr + j*4;
        *(float4*)&Qs[d*68 + f*4] = *(const float4*)&Qg[(size_t)d*SEQ + qt*64 + f*4];
        *(float4*)&Ks[d*68 + f*4] = *(const float4*)&Kg[(size_t)d*SEQ + kt*64 + f*4];
    }
    __syncthreads();

    ull acc[8][4];
    #pragma unroll
    for (int i = 0; i < 8; i++)
        #pragma unroll
        for (int j = 0; j < 4; j++) acc[i][j] = 0ULL;

    #pragma unroll 16
    for (int kk = 0; kk < 64; kk++) MAINSTEP(&Qs[kk*68], &Ks[kk*68]);

    const int k0 = kt*64 + tx*8;
    int kf[8];
    #pragma unroll
    for (int j = 0; j < 8; j++) kf[j] = (k0 + j) / 25;

    #pragma unroll
    for (int i = 0; i < 8; i++) {
        const int qi = qt*64 + ty*8 + i;
        const int qf = qi / 25;
        float e[8];
        #pragma unroll
        for (int j = 0; j < 4; j++) {
            float2 t = upk2(acc[i][j]);
            e[j*2] = t.x; e[j*2+1] = t.y;
        }
        #pragma unroll
        for (int j = 0; j < 8; j++)
            e[j] = (qf != kf[j] || qi == k0 + j) ? __expf(e[j]) : 0.f;

        float* pr = &p[((size_t)bh*SEQ + qi)*SEQ + k0];
        *(float4*)pr       = make_float4(e[0], e[1], e[2], e[3]);
        *(float4*)(pr + 4) = make_float4(e[4], e[5], e[6], e[7]);

        float r = ((e[0]+e[1])+(e[2]+e[3])) + ((e[4]+e[5])+(e[6]+e[7]));
        r += __shfl_down_sync(0xffffffffu, r, 4, 8);
        r += __shfl_down_sync(0xffffffffu, r, 2, 8);
        r += __shfl_down_sync(0xffffffffu, r, 1, 8);
        if (tx == 0) g_partial[((size_t)bh*SEQ + qi)*25 + kt] = r;
    }
}

// ================= K3: row inverse =================
__global__ __launch_bounds__(256) void rowinv_kernel()
{
    const int row = blockIdx.x*256 + threadIdx.x;
    if (row >= BH*SEQ) return;
    float s = 0.f;
    #pragma unroll
    for (int t = 0; t < 25; t++) s += g_partial[(size_t)row*25 + t];
    g_rowinv[row] = 1.0f / s;
}

// ================= K4: normalize p in place + out = P @ V =================
__global__ __launch_bounds__(64) void pv_kernel(float* __restrict__ p, float* __restrict__ out)
{
    __shared__ __align__(16) float Es[64*68];   // [s][q]
    __shared__ __align__(16) float Vs[64*68];   // [s][d]
    __shared__ float rs[64];
    const int tid = threadIdx.x, tx = tid & 7, ty = tid >> 3;
    const int qt = blockIdx.x, bh = blockIdx.y;

    rs[tid] = g_rowinv[(size_t)bh*SEQ + qt*64 + tid];
    __syncthreads();
    const float rv = rs[tid];

    ull acc[8][4];
    #pragma unroll
    for (int i = 0; i < 8; i++)
        #pragma unroll
        for (int j = 0; j < 4; j++) acc[i][j] = 0ULL;

    const int f = tid & 15, r4 = tid >> 4;

    for (int kt = 0; kt < 25; kt++) {
        // e row (q = tid): load, normalize, write back, transpose into smem
        float* pr = p + ((size_t)bh*SEQ + qt*64 + tid)*SEQ + kt*64;
        #pragma unroll
        for (int j = 0; j < 16; j++) {
            float4 e4 = *(const float4*)&pr[j*4];
            e4.x *= rv; e4.y *= rv; e4.z *= rv; e4.w *= rv;
            *(float4*)&pr[j*4] = e4;
            Es[(j*4+0)*68 + tid] = e4.x;
            Es[(j*4+1)*68 + tid] = e4.y;
            Es[(j*4+2)*68 + tid] = e4.z;
            Es[(j*4+3)*68 + tid] = e4.w;
        }
        // V tile natural [s][d]
        const float* Vg = g_v + ((size_t)bh*SEQ + kt*64)*64;
        #pragma unroll
        for (int j = 0; j < 16; j++) {
            const int s = r4 + j*4;
            *(float4*)&Vs[s*68 + f*4] = *(const float4*)&Vg[(size_t)s*64 + f*4];
        }
        __syncthreads();
        #pragma unroll 16
        for (int kk = 0; kk < 64; kk++) MAINSTEP(&Es[kk*68], &Vs[kk*68]);
        __syncthreads();
    }

    const int b = bh >> 3, h = bh & 7;
    #pragma unroll
    for (int i = 0; i < 8; i++) {
        const int s = qt*64 + ty*8 + i;
        float2 t0 = upk2(acc[i][0]), t1 = upk2(acc[i][1]);
        float2 t2 = upk2(acc[i][2]), t3 = upk2(acc[i][3]);
        float* orow = &out[((size_t)(b*SEQ + s))*512 + h*64 + tx*8];
        *(float4*)orow       = make_float4(t0.x, t0.y, t1.x, t1.y);
        *(float4*)(orow + 4) = make_float4(t2.x, t2.y, t3.x, t3.y);
    }
}

extern "C" void kernel_launch(void* const* d_in, const int* in_sizes, int n_in,
                              void* d_out, int out_size)
{
    const float* x  = (const float*)d_in[0];
    const float* wq = (const float*)d_in[1];
    const float* bq = (const float*)d_in[2];
    const float* wk = (const float*)d_in[3];
    const float* bk = (const float*)d_in[4];
    const float* wv = (const float*)d_in[5];
    const float* bv = (const float*)d_in[6];
    float* out = (float*)d_out;
    float* p   = out + OUT_ELEMS;

    proj_kernel<<<dim3(200, 8, 3), 64>>>(x, wq, bq, wk, bk, wv, bv);
    score_kernel<<<dim3(25, 25, BH), 64>>>(p);
    rowinv_kernel<<<dim3(400), 256>>>();
    pv_kernel<<<dim3(25, BH), 64>>>(p, out);
}

// round 5
// speedup vs baseline: 1.2805x; 1.2746x over previous
#include <cuda_runtime.h>
#include <cuda_bf16.h>
#include <cstdint>

#define SEQ 1600
#define SP  1664          /* padded seq: 13 * 128 */
#define BH  64
#define NKT 13
#define OUT_ELEMS (8*SEQ*512)

// -------------------- scratch (device globals, zero-initialized) --------------------
__device__ __nv_bfloat16 g_qh[(size_t)BH*SP*64];
__device__ __nv_bfloat16 g_ql[(size_t)BH*SP*64];
__device__ __nv_bfloat16 g_kh[(size_t)BH*SP*64];
__device__ __nv_bfloat16 g_kl[(size_t)BH*SP*64];
__device__ float g_v[(size_t)BH*SEQ*64];
__device__ float g_partial[(size_t)BH*SEQ*NKT];
__device__ float g_rowinv[(size_t)BH*SEQ];

// -------------------- f32x2 helpers --------------------
typedef unsigned long long ull;
__device__ __forceinline__ ull pk2(float a, float b) {
    ull r; asm("mov.b64 %0, {%1, %2};" : "=l"(r) : "f"(a), "f"(b)); return r;
}
__device__ __forceinline__ float2 upk2(ull v) {
    float2 f; asm("mov.b64 {%0, %1}, %2;" : "=f"(f.x), "=f"(f.y) : "l"(v)); return f;
}
__device__ __forceinline__ ull fma2(ull a, ull b, ull c) {
    ull d; asm("fma.rn.f32x2 %0, %1, %2, %3;" : "=l"(d) : "l"(a), "l"(b), "l"(c)); return d;
}

// 8x8 micro-tile step (uses acc[8][4], tx, ty from scope)
#define MAINSTEP(As_row, Bs_row) do {                                   \
    const float4 a0 = *(const float4*)((As_row) + ty*8);                \
    const float4 a1 = *(const float4*)((As_row) + ty*8 + 4);            \
    const ulonglong2 b0 = *(const ulonglong2*)((Bs_row) + tx*8);        \
    const ulonglong2 b1 = *(const ulonglong2*)((Bs_row) + tx*8 + 4);    \
    const float av[8] = {a0.x,a0.y,a0.z,a0.w,a1.x,a1.y,a1.z,a1.w};      \
    _Pragma("unroll")                                                   \
    for (int _i = 0; _i < 8; _i++) {                                    \
        const ull aa = pk2(av[_i], av[_i]);                             \
        acc[_i][0] = fma2(aa, b0.x, acc[_i][0]);                        \
        acc[_i][1] = fma2(aa, b0.y, acc[_i][1]);                        \
        acc[_i][2] = fma2(aa, b1.x, acc[_i][2]);                        \
        acc[_i][3] = fma2(aa, b1.y, acc[_i][3]);                        \
    } } while (0)

// -------------------- mma.sync / ldmatrix helpers (baseline PTX, sm_80+) --------------------
__device__ __forceinline__ uint32_t smem_u32(const void* p_) {
    uint32_t a;
    asm("{ .reg .u64 t; cvta.to.shared.u64 t, %1; cvt.u32.u64 %0, t; }" : "=r"(a) : "l"(p_));
    return a;
}
__device__ __forceinline__ void ldsm4(uint32_t* r, uint32_t addr) {
    asm volatile("ldmatrix.sync.aligned.m8n8.x4.shared.b16 {%0,%1,%2,%3}, [%4];"
                 : "=r"(r[0]), "=r"(r[1]), "=r"(r[2]), "=r"(r[3]) : "r"(addr));
}
__device__ __forceinline__ void mma16816(float* d, const uint32_t* a, const uint32_t* b) {
    asm volatile("mma.sync.aligned.m16n8k16.row.col.f32.bf16.bf16.f32 "
                 "{%0,%1,%2,%3}, {%4,%5,%6,%7}, {%8,%9}, {%0,%1,%2,%3};"
                 : "+f"(d[0]), "+f"(d[1]), "+f"(d[2]), "+f"(d[3])
                 : "r"(a[0]), "r"(a[1]), "r"(a[2]), "r"(a[3]), "r"(b[0]), "r"(b[1]));
}

// ==================== K1: QKV projection (256 thr, 128x128 tiles) ====================
__global__ __launch_bounds__(256) void proj_kernel(
    const float* __restrict__ x,
    const float* __restrict__ wq, const float* __restrict__ bq,
    const float* __restrict__ wk, const float* __restrict__ bk,
    const float* __restrict__ wv, const float* __restrict__ bv)
{
    __shared__ __align__(16) float As[16*132];
    __shared__ __align__(16) float Bs[16*132];
    const int tid = threadIdx.x, tx = tid & 15, ty = tid >> 4;
    const int m0 = blockIdx.x*128, n0 = blockIdx.y*128, mat = blockIdx.z;
    const float* w  = (mat==0) ? wq : ((mat==1) ? wk : wv);
    const float* bb = (mat==0) ? bq : ((mat==1) ? bk : bv);

    ull acc[8][4];
    #pragma unroll
    for (int i = 0; i < 8; i++)
        #pragma unroll
        for (int j = 0; j < 4; j++) acc[i][j] = 0ULL;

    for (int kc = 0; kc < 256; kc += 16) {
        #pragma unroll
        for (int j = 0; j < 2; j++) {
            const int idx = tid + j*256;
            const int r = idx >> 2, c4 = idx & 3;
            float4 v = *(const float4*)&x[(size_t)(m0 + r)*256 + kc + c4*4];
            As[(c4*4+0)*132 + r] = v.x;
            As[(c4*4+1)*132 + r] = v.y;
            As[(c4*4+2)*132 + r] = v.z;
            As[(c4*4+3)*132 + r] = v.w;
        }
        #pragma unroll
        for (int j = 0; j < 2; j++) {
            const int idx = tid + j*256;
            const int r = idx >> 5, c = idx & 31;
            *(float4*)&Bs[r*132 + c*4] = *(const float4*)&w[(size_t)(kc + r)*512 + n0 + c*4];
        }
        __syncthreads();
        #pragma unroll
        for (int kk = 0; kk < 16; kk++) MAINSTEP(&As[kk*132], &Bs[kk*132]);
        __syncthreads();
    }

    const int n_base = n0 + tx*8;
    const int h = n_base >> 6, d0 = n_base & 63;
    float b8[8];
    #pragma unroll
    for (int j = 0; j < 8; j++) b8[j] = bb[n_base + j];

    #pragma unroll
    for (int i = 0; i < 8; i++) {
        const int m = m0 + ty*8 + i;
        const int bI = m / SEQ, sI = m % SEQ;
        const int bh = bI*8 + h;
        float o[8];
        #pragma unroll
        for (int j = 0; j < 4; j++) {
            float2 t = upk2(acc[i][j]);
            o[j*2] = t.x + b8[j*2]; o[j*2+1] = t.y + b8[j*2+1];
        }
        if (mat == 2) {
            #pragma unroll
            for (int j = 0; j < 8; j++) o[j] = fmaxf(o[j], 0.f);
            float* dr = &g_v[((size_t)bh*SEQ + sI)*64 + d0];
            *(float4*)dr       = make_float4(o[0], o[1], o[2], o[3]);
            *(float4*)(dr + 4) = make_float4(o[4], o[5], o[6], o[7]);
        } else {
            if (mat == 0) {
                #pragma unroll
                for (int j = 0; j < 8; j++) o[j] *= 0.125f;
            }
            uint32_t hw[4], lw[4];
            #pragma unroll
            for (int j = 0; j < 4; j++) {
                __nv_bfloat16 h0 = __float2bfloat16(o[j*2]);
                __nv_bfloat16 h1 = __float2bfloat16(o[j*2+1]);
                __nv_bfloat16 l0 = __float2bfloat16(o[j*2]   - __bfloat162float(h0));
                __nv_bfloat16 l1 = __float2bfloat16(o[j*2+1] - __bfloat162float(h1));
                hw[j] = (uint32_t)__bfloat16_as_ushort(h0) | ((uint32_t)__bfloat16_as_ushort(h1) << 16);
                lw[j] = (uint32_t)__bfloat16_as_ushort(l0) | ((uint32_t)__bfloat16_as_ushort(l1) << 16);
            }
            const size_t off = ((size_t)bh*SP + sI)*64 + d0;
            __nv_bfloat16* dh = (mat == 0) ? g_qh : g_kh;
            __nv_bfloat16* dl = (mat == 0) ? g_ql : g_kl;
            *(uint4*)&dh[off] = make_uint4(hw[0], hw[1], hw[2], hw[3]);
            *(uint4*)&dl[off] = make_uint4(lw[0], lw[1], lw[2], lw[3]);
        }
    }
}

// ==================== K2: mma.sync score tile (64q x 128k) ====================
// smem (halves): QH [64][72], QL [64][72], KH [128][72], KL [128][72]
#define SC_SMEM_BYTES (27648*2)

__global__ __launch_bounds__(128) void score_kernel(float* __restrict__ p)
{
    extern __shared__ __align__(16) __nv_bfloat16 sm[];
    __nv_bfloat16* QH = sm;
    __nv_bfloat16* QL = sm + 4608;
    __nv_bfloat16* KH = sm + 9216;
    __nv_bfloat16* KL = sm + 18432;
    __shared__ float sums[4][64];

    const int tid = threadIdx.x, w = tid >> 5, lane = tid & 31;
    const int kt = blockIdx.x, qt = blockIdx.y, bh = blockIdx.z;
    const int q0 = qt*64, k0 = kt*128;

    // ---- load tiles (rows padded to 72 halves = 144B) ----
    {
        const uint4* sqh = (const uint4*)(g_qh + ((size_t)bh*SP + q0)*64);
        const uint4* sql = (const uint4*)(g_ql + ((size_t)bh*SP + q0)*64);
        #pragma unroll
        for (int it = 0; it < 4; it++) {
            const int i = tid + it*128;            // 0..511 : row = i/8, chunk = i%8
            const int r = i >> 3, c = i & 7;
            *(uint4*)&QH[r*72 + c*8] = sqh[i];
            *(uint4*)&QL[r*72 + c*8] = sql[i];
        }
        const uint4* skh = (const uint4*)(g_kh + ((size_t)bh*SP + k0)*64);
        const uint4* skl = (const uint4*)(g_kl + ((size_t)bh*SP + k0)*64);
        #pragma unroll
        for (int it = 0; it < 8; it++) {
            const int i = tid + it*128;            // 0..1023
            const int r = i >> 3, c = i & 7;
            *(uint4*)&KH[r*72 + c*8] = skh[i];
            *(uint4*)&KL[r*72 + c*8] = skl[i];
        }
    }
    __syncthreads();

    float acc[4][4][4];
    #pragma unroll
    for (int a = 0; a < 4; a++)
        #pragma unroll
        for (int b = 0; b < 4; b++)
            #pragma unroll
            for (int c = 0; c < 4; c++) acc[a][b][c] = 0.f;

    const uint32_t aQH = smem_u32(QH), aQL = smem_u32(QL);
    const uint32_t aKH = smem_u32(KH), aKL = smem_u32(KL);

    // A addressing: lanes 0-15 -> rows (mb*16 + lane&15) @ k, lanes 16-31 same rows @ k+8
    const int arow = lane & 15, akoff8 = (lane >> 4) * 8;
    // B addressing: 8-lane groups -> mats (n0-7,k0),(n0-7,k8),(n8-15,k0),(n8-15,k8)
    const int mi = lane >> 3, l8 = lane & 7;
    const int brow = (mi >> 1)*8 + l8, bkoff8 = (mi & 1)*8;

    #pragma unroll
    for (int kc = 0; kc < 4; kc++) {
        uint32_t ah[4][4], al[4][4], bhf[2][4], blf[2][4];
        const int ak = kc*16 + akoff8;
        #pragma unroll
        for (int mb = 0; mb < 4; mb++) {
            const uint32_t off = (uint32_t)(((mb*16 + arow)*72 + ak) * 2);
            ldsm4(ah[mb], aQH + off);
            ldsm4(al[mb], aQL + off);
        }
        const int bk = kc*16 + bkoff8;
        #pragma unroll
        for (int nbp = 0; nbp < 2; nbp++) {
            const int n = w*32 + nbp*16 + brow;
            const uint32_t off = (uint32_t)((n*72 + bk) * 2);
            ldsm4(bhf[nbp], aKH + off);
            ldsm4(blf[nbp], aKL + off);
        }
        #pragma unroll
        for (int mb = 0; mb < 4; mb++)
            #pragma unroll
            for (int nb = 0; nb < 4; nb++) {
                const int nbp = nb >> 1, sel = (nb & 1)*2;
                mma16816(acc[mb][nb], ah[mb], &bhf[nbp][sel]);
                mma16816(acc[mb][nb], ah[mb], &blf[nbp][sel]);
                mma16816(acc[mb][nb], al[mb], &bhf[nbp][sel]);
            }
    }

    // ---- epilogue: mask, exp, store e, rowsums ----
    const int r0 = lane >> 2;          // 0..7
    const int c0 = (lane & 3) * 2;     // 0,2,4,6
    #pragma unroll
    for (int mb = 0; mb < 4; mb++) {
        const int q1 = q0 + mb*16 + r0, q2 = q1 + 8;
        const int qf1 = q1 / 25, qf2 = q2 / 25;
        float s1 = 0.f, s2 = 0.f;
        #pragma unroll
        for (int nb = 0; nb < 4; nb++) {
            const int k = k0 + w*32 + nb*8 + c0;
            const int kfa = k / 25, kfb = (k + 1) / 25;
            const bool kv = (k < SEQ);
            float e0 = (kv && (qf1 != kfa || q1 == k  )) ? __expf(acc[mb][nb][0]) : 0.f;
            float e1 = (kv && (qf1 != kfb || q1 == k+1)) ? __expf(acc[mb][nb][1]) : 0.f;
            float e2 = (kv && (qf2 != kfa || q2 == k  )) ? __expf(acc[mb][nb][2]) : 0.f;
            float e3 = (kv && (qf2 != kfb || q2 == k+1)) ? __expf(acc[mb][nb][3]) : 0.f;
            s1 += e0 + e1; s2 += e2 + e3;
            if (kv) {
                if (q1 < SEQ) *(float2*)&p[((size_t)bh*SEQ + q1)*SEQ + k] = make_float2(e0, e1);
                if (q2 < SEQ) *(float2*)&p[((size_t)bh*SEQ + q2)*SEQ + k] = make_float2(e2, e3);
            }
        }
        s1 += __shfl_xor_sync(0xffffffffu, s1, 1);
        s1 += __shfl_xor_sync(0xffffffffu, s1, 2);
        s2 += __shfl_xor_sync(0xffffffffu, s2, 1);
        s2 += __shfl_xor_sync(0xffffffffu, s2, 2);
        if ((lane & 3) == 0) {
            sums[w][mb*16 + r0]     = s1;
            sums[w][mb*16 + 8 + r0] = s2;
        }
    }
    __syncthreads();
    if (tid < 64) {
        const int q = q0 + tid;
        if (q < SEQ)
            g_partial[((size_t)bh*SEQ + q)*NKT + kt] =
                (sums[0][tid] + sums[1][tid]) + (sums[2][tid] + sums[3][tid]);
    }
}

// ==================== K3: row inverse ====================
__global__ __launch_bounds__(256) void rowinv_kernel()
{
    const int row = blockIdx.x*256 + threadIdx.x;
    if (row >= BH*SEQ) return;
    float s = 0.f;
    #pragma unroll
    for (int t = 0; t < NKT; t++) s += g_partial[(size_t)row*NKT + t];
    g_rowinv[row] = 1.0f / s;
}

// ==================== K4: normalize p in place + out = P @ V ====================
__global__ __launch_bounds__(128) void pv_kernel(float* __restrict__ p, float* __restrict__ out)
{
    __shared__ __align__(16) float Es[32*132];   // [s][q]
    __shared__ __align__(16) float Vs[32*68];    // [s][d]
    const int tid = threadIdx.x, tx = tid & 7, ty = tid >> 3;
    const int qt = blockIdx.x, bh = blockIdx.y;
    const int q0 = qt*128;

    const int qrow = q0 + tid;
    const int rq = (qrow < SEQ) ? qrow : (SEQ - 1);
    const bool wb = (qrow < SEQ);
    const float rv = g_rowinv[(size_t)bh*SEQ + rq];
    float* prow = p + ((size_t)bh*SEQ + rq)*SEQ;
    const float* vbase = g_v + (size_t)bh*SEQ*64;

    ull acc[8][4];
    #pragma unroll
    for (int i = 0; i < 8; i++)
        #pragma unroll
        for (int j = 0; j < 4; j++) acc[i][j] = 0ULL;

    for (int kt = 0; kt < 50; kt++) {
        const int s0 = kt*32;
        #pragma unroll
        for (int j = 0; j < 8; j++) {
            float4 e4 = *(const float4*)&prow[s0 + j*4];
            e4.x *= rv; e4.y *= rv; e4.z *= rv; e4.w *= rv;
            if (wb) *(float4*)&prow[s0 + j*4] = e4;
            Es[(j*4+0)*132 + tid] = e4.x;
            Es[(j*4+1)*132 + tid] = e4.y;
            Es[(j*4+2)*132 + tid] = e4.z;
            Es[(j*4+3)*132 + tid] = e4.w;
        }
        #pragma unroll
        for (int j = 0; j < 4; j++) {
            const int idx = tid + j*128;
            const int r = idx >> 4, c = idx & 15;
            *(float4*)&Vs[r*68 + c*4] = *(const float4*)&vbase[(size_t)(s0 + r)*64 + c*4];
        }
        __syncthreads();
        #pragma unroll
        for (int kk = 0; kk < 32; kk++) MAINSTEP(&Es[kk*132], &Vs[kk*68]);
        __syncthreads();
    }

    const int b = bh >> 3, h = bh & 7;
    #pragma unroll
    for (int i = 0; i < 8; i++) {
        const int q = q0 + ty*8 + i;
        if (q < SEQ) {
            float2 t0 = upk2(acc[i][0]), t1 = upk2(acc[i][1]);
            float2 t2 = upk2(acc[i][2]), t3 = upk2(acc[i][3]);
            float* orow = &out[((size_t)(b*SEQ + q))*512 + h*64 + tx*8];
            *(float4*)orow       = make_float4(t0.x, t0.y, t1.x, t1.y);
            *(float4*)(orow + 4) = make_float4(t2.x, t2.y, t3.x, t3.y);
        }
    }
}

extern "C" void kernel_launch(void* const* d_in, const int* in_sizes, int n_in,
                              void* d_out, int out_size)
{
    const float* x  = (const float*)d_in[0];
    const float* wq = (const float*)d_in[1];
    const float* bq = (const float*)d_in[2];
    const float* wk = (const float*)d_in[3];
    const float* bk = (const float*)d_in[4];
    const float* wv = (const float*)d_in[5];
    const float* bv = (const float*)d_in[6];
    float* out = (float*)d_out;
    float* p   = out + OUT_ELEMS;

    cudaFuncSetAttribute(score_kernel, cudaFuncAttributeMaxDynamicSharedMemorySize, SC_SMEM_BYTES);

    proj_kernel<<<dim3(100, 4, 3), 256>>>(x, wq, bq, wk, bk, wv, bv);
    score_kernel<<<dim3(NKT, 26, BH), 128, SC_SMEM_BYTES>>>(p);
    rowinv_kernel<<<dim3((BH*SEQ + 255)/256), 256>>>();
    pv_kernel<<<dim3(NKT, BH), 128>>>(p, out);
}

// round 6
// speedup vs baseline: 1.4021x; 1.0950x over previous
#include <cuda_runtime.h>
#include <cuda_bf16.h>
#include <cstdint>

#define SEQ 1600
#define SP  1664          /* padded seq: 13 * 128 */
#define BH  64
#define NKT 13
#define OUT_ELEMS (8*SEQ*512)

// -------------------- scratch (device globals, zero-initialized) --------------------
__device__ __nv_bfloat16 g_qh[(size_t)BH*SP*64];
__device__ __nv_bfloat16 g_ql[(size_t)BH*SP*64];
__device__ __nv_bfloat16 g_kh[(size_t)BH*SP*64];
__device__ __nv_bfloat16 g_kl[(size_t)BH*SP*64];
__device__ __nv_bfloat16 g_vh[(size_t)BH*64*SEQ];   // [bh][d][s] transposed
__device__ __nv_bfloat16 g_vl[(size_t)BH*64*SEQ];
__device__ float g_partial[(size_t)BH*SEQ*NKT];
__device__ float g_rowinv[(size_t)BH*SEQ];

// -------------------- f32x2 helpers --------------------
typedef unsigned long long ull;
__device__ __forceinline__ ull pk2(float a, float b) {
    ull r; asm("mov.b64 %0, {%1, %2};" : "=l"(r) : "f"(a), "f"(b)); return r;
}
__device__ __forceinline__ float2 upk2(ull v) {
    float2 f; asm("mov.b64 {%0, %1}, %2;" : "=f"(f.x), "=f"(f.y) : "l"(v)); return f;
}
__device__ __forceinline__ ull fma2(ull a, ull b, ull c) {
    ull d; asm("fma.rn.f32x2 %0, %1, %2, %3;" : "=l"(d) : "l"(a), "l"(b), "l"(c)); return d;
}

#define MAINSTEP(As_row, Bs_row) do {                                   \
    const float4 a0 = *(const float4*)((As_row) + ty*8);                \
    const float4 a1 = *(const float4*)((As_row) + ty*8 + 4);            \
    const ulonglong2 b0 = *(const ulonglong2*)((Bs_row) + tx*8);        \
    const ulonglong2 b1 = *(const ulonglong2*)((Bs_row) + tx*8 + 4);    \
    const float av[8] = {a0.x,a0.y,a0.z,a0.w,a1.x,a1.y,a1.z,a1.w};      \
    _Pragma("unroll")                                                   \
    for (int _i = 0; _i < 8; _i++) {                                    \
        const ull aa = pk2(av[_i], av[_i]);                             \
        acc[_i][0] = fma2(aa, b0.x, acc[_i][0]);                        \
        acc[_i][1] = fma2(aa, b0.y, acc[_i][1]);                        \
        acc[_i][2] = fma2(aa, b1.x, acc[_i][2]);                        \
        acc[_i][3] = fma2(aa, b1.y, acc[_i][3]);                        \
    } } while (0)

// -------------------- mma.sync / ldmatrix helpers --------------------
__device__ __forceinline__ uint32_t smem_u32(const void* p_) {
    uint32_t a;
    asm("{ .reg .u64 t; cvta.to.shared.u64 t, %1; cvt.u32.u64 %0, t; }" : "=r"(a) : "l"(p_));
    return a;
}
__device__ __forceinline__ void ldsm4(uint32_t* r, uint32_t addr) {
    asm volatile("ldmatrix.sync.aligned.m8n8.x4.shared.b16 {%0,%1,%2,%3}, [%4];"
                 : "=r"(r[0]), "=r"(r[1]), "=r"(r[2]), "=r"(r[3]) : "r"(addr));
}
__device__ __forceinline__ void mma16816(float* d, const uint32_t* a, const uint32_t* b) {
    asm volatile("mma.sync.aligned.m16n8k16.row.col.f32.bf16.bf16.f32 "
                 "{%0,%1,%2,%3}, {%4,%5,%6,%7}, {%8,%9}, {%0,%1,%2,%3};"
                 : "+f"(d[0]), "+f"(d[1]), "+f"(d[2]), "+f"(d[3])
                 : "r"(a[0]), "r"(a[1]), "r"(a[2]), "r"(a[3]), "r"(b[0]), "r"(b[1]));
}

// ==================== K1: QKV projection (256 thr, 128x128 tiles) ====================
__global__ __launch_bounds__(256) void proj_kernel(
    const float* __restrict__ x,
    const float* __restrict__ wq, const float* __restrict__ bq,
    const float* __restrict__ wk, const float* __restrict__ bk,
    const float* __restrict__ wv, const float* __restrict__ bv)
{
    __shared__ __align__(16) float As[16*132];
    __shared__ __align__(16) float Bs[16*132];
    const int tid = threadIdx.x, tx = tid & 15, ty = tid >> 4;
    const int m0 = blockIdx.x*128, n0 = blockIdx.y*128, mat = blockIdx.z;
    const float* w  = (mat==0) ? wq : ((mat==1) ? wk : wv);
    const float* bb = (mat==0) ? bq : ((mat==1) ? bk : bv);

    ull acc[8][4];
    #pragma unroll
    for (int i = 0; i < 8; i++)
        #pragma unroll
        for (int j = 0; j < 4; j++) acc[i][j] = 0ULL;

    for (int kc = 0; kc < 256; kc += 16) {
        #pragma unroll
        for (int j = 0; j < 2; j++) {
            const int idx = tid + j*256;
            const int r = idx >> 2, c4 = idx & 3;
            float4 v = *(const float4*)&x[(size_t)(m0 + r)*256 + kc + c4*4];
            As[(c4*4+0)*132 + r] = v.x;
            As[(c4*4+1)*132 + r] = v.y;
            As[(c4*4+2)*132 + r] = v.z;
            As[(c4*4+3)*132 + r] = v.w;
        }
        #pragma unroll
        for (int j = 0; j < 2; j++) {
            const int idx = tid + j*256;
            const int r = idx >> 5, c = idx & 31;
            *(float4*)&Bs[r*132 + c*4] = *(const float4*)&w[(size_t)(kc + r)*512 + n0 + c*4];
        }
        __syncthreads();
        #pragma unroll
        for (int kk = 0; kk < 16; kk++) MAINSTEP(&As[kk*132], &Bs[kk*132]);
        __syncthreads();
    }

    const int n_base = n0 + tx*8;
    const int h = n_base >> 6, d0 = n_base & 63;
    float b8[8];
    #pragma unroll
    for (int j = 0; j < 8; j++) b8[j] = bb[n_base + j];

    const int m_base = m0 + ty*8;
    const int bI = m_base / SEQ, sI0 = m_base % SEQ;   // 8-row group never crosses batch
    const int bh = bI*8 + h;

    if (mat == 2) {
        // V: relu, split bf16 hi/lo, store transposed [bh][d][s]
        #pragma unroll
        for (int j = 0; j < 8; j++) {
            uint32_t hp[4], lp[4];
            #pragma unroll
            for (int i2 = 0; i2 < 4; i2++) {
                float v0, v1;
                {
                    float2 t = upk2(acc[i2*2][j>>1]);
                    v0 = ((j & 1) ? t.y : t.x) + b8[j];
                }
                {
                    float2 t = upk2(acc[i2*2+1][j>>1]);
                    v1 = ((j & 1) ? t.y : t.x) + b8[j];
                }
                v0 = fmaxf(v0, 0.f); v1 = fmaxf(v1, 0.f);
                __nv_bfloat16 h0 = __float2bfloat16(v0), h1 = __float2bfloat16(v1);
                __nv_bfloat16 l0 = __float2bfloat16(v0 - __bfloat162float(h0));
                __nv_bfloat16 l1 = __float2bfloat16(v1 - __bfloat162float(h1));
                hp[i2] = (uint32_t)__bfloat16_as_ushort(h0) | ((uint32_t)__bfloat16_as_ushort(h1) << 16);
                lp[i2] = (uint32_t)__bfloat16_as_ushort(l0) | ((uint32_t)__bfloat16_as_ushort(l1) << 16);
            }
            const size_t off = ((size_t)bh*64 + d0 + j)*SEQ + sI0;
            *(uint4*)&g_vh[off] = make_uint4(hp[0], hp[1], hp[2], hp[3]);
            *(uint4*)&g_vl[off] = make_uint4(lp[0], lp[1], lp[2], lp[3]);
        }
    } else {
        const float sc = (mat == 0) ? 0.125f : 1.0f;
        __nv_bfloat16* dh = (mat == 0) ? g_qh : g_kh;
        __nv_bfloat16* dl = (mat == 0) ? g_ql : g_kl;
        #pragma unroll
        for (int i = 0; i < 8; i++) {
            float o[8];
            #pragma unroll
            for (int j = 0; j < 4; j++) {
                float2 t = upk2(acc[i][j]);
                o[j*2] = (t.x + b8[j*2]) * sc; o[j*2+1] = (t.y + b8[j*2+1]) * sc;
            }
            uint32_t hw[4], lw[4];
            #pragma unroll
            for (int j = 0; j < 4; j++) {
                __nv_bfloat16 h0 = __float2bfloat16(o[j*2]);
                __nv_bfloat16 h1 = __float2bfloat16(o[j*2+1]);
                __nv_bfloat16 l0 = __float2bfloat16(o[j*2]   - __bfloat162float(h0));
                __nv_bfloat16 l1 = __float2bfloat16(o[j*2+1] - __bfloat162float(h1));
                hw[j] = (uint32_t)__bfloat16_as_ushort(h0) | ((uint32_t)__bfloat16_as_ushort(h1) << 16);
                lw[j] = (uint32_t)__bfloat16_as_ushort(l0) | ((uint32_t)__bfloat16_as_ushort(l1) << 16);
            }
            const size_t off = ((size_t)bh*SP + sI0 + i)*64 + d0;
            *(uint4*)&dh[off] = make_uint4(hw[0], hw[1], hw[2], hw[3]);
            *(uint4*)&dl[off] = make_uint4(lw[0], lw[1], lw[2], lw[3]);
        }
    }
}

// ==================== K2: mma.sync score tile (64q x 128k) ====================
#define SC_SMEM_BYTES (27648*2)

__global__ __launch_bounds__(128) void score_kernel(float* __restrict__ p)
{
    extern __shared__ __align__(16) __nv_bfloat16 sm[];
    __nv_bfloat16* QH = sm;
    __nv_bfloat16* QL = sm + 4608;
    __nv_bfloat16* KH = sm + 9216;
    __nv_bfloat16* KL = sm + 18432;
    __shared__ float sums[4][64];

    const int tid = threadIdx.x, w = tid >> 5, lane = tid & 31;
    const int kt = blockIdx.x, qt = blockIdx.y, bh = blockIdx.z;
    const int q0 = qt*64, k0 = kt*128;

    {
        const uint4* sqh = (const uint4*)(g_qh + ((size_t)bh*SP + q0)*64);
        const uint4* sql = (const uint4*)(g_ql + ((size_t)bh*SP + q0)*64);
        #pragma unroll
        for (int it = 0; it < 4; it++) {
            const int i = tid + it*128;
            const int r = i >> 3, c = i & 7;
            *(uint4*)&QH[r*72 + c*8] = sqh[i];
            *(uint4*)&QL[r*72 + c*8] = sql[i];
        }
        const uint4* skh = (const uint4*)(g_kh + ((size_t)bh*SP + k0)*64);
        const uint4* skl = (const uint4*)(g_kl + ((size_t)bh*SP + k0)*64);
        #pragma unroll
        for (int it = 0; it < 8; it++) {
            const int i = tid + it*128;
            const int r = i >> 3, c = i & 7;
            *(uint4*)&KH[r*72 + c*8] = skh[i];
            *(uint4*)&KL[r*72 + c*8] = skl[i];
        }
    }
    __syncthreads();

    float acc[4][4][4];
    #pragma unroll
    for (int a = 0; a < 4; a++)
        #pragma unroll
        for (int b = 0; b < 4; b++)
            #pragma unroll
            for (int c = 0; c < 4; c++) acc[a][b][c] = 0.f;

    const uint32_t aQH = smem_u32(QH), aQL = smem_u32(QL);
    const uint32_t aKH = smem_u32(KH), aKL = smem_u32(KL);

    const int arow = lane & 15, akoff8 = (lane >> 4) * 8;
    const int mi = lane >> 3, l8 = lane & 7;
    const int brow = (mi >> 1)*8 + l8, bkoff8 = (mi & 1)*8;

    #pragma unroll
    for (int kc = 0; kc < 4; kc++) {
        uint32_t ah[4][4], al[4][4], bhf[2][4], blf[2][4];
        const int ak = kc*16 + akoff8;
        #pragma unroll
        for (int mb = 0; mb < 4; mb++) {
            const uint32_t off = (uint32_t)(((mb*16 + arow)*72 + ak) * 2);
            ldsm4(ah[mb], aQH + off);
            ldsm4(al[mb], aQL + off);
        }
        const int bk = kc*16 + bkoff8;
        #pragma unroll
        for (int nbp = 0; nbp < 2; nbp++) {
            const int n = w*32 + nbp*16 + brow;
            const uint32_t off = (uint32_t)((n*72 + bk) * 2);
            ldsm4(bhf[nbp], aKH + off);
            ldsm4(blf[nbp], aKL + off);
        }
        #pragma unroll
        for (int mb = 0; mb < 4; mb++)
            #pragma unroll
            for (int nb = 0; nb < 4; nb++) {
                const int nbp = nb >> 1, sel = (nb & 1)*2;
                mma16816(acc[mb][nb], ah[mb], &bhf[nbp][sel]);
                mma16816(acc[mb][nb], ah[mb], &blf[nbp][sel]);
                mma16816(acc[mb][nb], al[mb], &bhf[nbp][sel]);
            }
    }

    const int r0 = lane >> 2;
    const int c0 = (lane & 3) * 2;
    #pragma unroll
    for (int mb = 0; mb < 4; mb++) {
        const int q1 = q0 + mb*16 + r0, q2 = q1 + 8;
        const int qf1 = q1 / 25, qf2 = q2 / 25;
        float s1 = 0.f, s2 = 0.f;
        #pragma unroll
        for (int nb = 0; nb < 4; nb++) {
            const int k = k0 + w*32 + nb*8 + c0;
            const int kfa = k / 25, kfb = (k + 1) / 25;
            const bool kv = (k < SEQ);
            float e0 = (kv && (qf1 != kfa || q1 == k  )) ? __expf(acc[mb][nb][0]) : 0.f;
            float e1 = (kv && (qf1 != kfb || q1 == k+1)) ? __expf(acc[mb][nb][1]) : 0.f;
            float e2 = (kv && (qf2 != kfa || q2 == k  )) ? __expf(acc[mb][nb][2]) : 0.f;
            float e3 = (kv && (qf2 != kfb || q2 == k+1)) ? __expf(acc[mb][nb][3]) : 0.f;
            s1 += e0 + e1; s2 += e2 + e3;
            if (kv) {
                if (q1 < SEQ) *(float2*)&p[((size_t)bh*SEQ + q1)*SEQ + k] = make_float2(e0, e1);
                if (q2 < SEQ) *(float2*)&p[((size_t)bh*SEQ + q2)*SEQ + k] = make_float2(e2, e3);
            }
        }
        s1 += __shfl_xor_sync(0xffffffffu, s1, 1);
        s1 += __shfl_xor_sync(0xffffffffu, s1, 2);
        s2 += __shfl_xor_sync(0xffffffffu, s2, 1);
        s2 += __shfl_xor_sync(0xffffffffu, s2, 2);
        if ((lane & 3) == 0) {
            sums[w][mb*16 + r0]     = s1;
            sums[w][mb*16 + 8 + r0] = s2;
        }
    }
    __syncthreads();
    if (tid < 64) {
        const int q = q0 + tid;
        if (q < SEQ)
            g_partial[((size_t)bh*SEQ + q)*NKT + kt] =
                (sums[0][tid] + sums[1][tid]) + (sums[2][tid] + sums[3][tid]);
    }
}

// ==================== K3: row inverse ====================
__global__ __launch_bounds__(256) void rowinv_kernel()
{
    const int row = blockIdx.x*256 + threadIdx.x;
    if (row >= BH*SEQ) return;
    float s = 0.f;
    #pragma unroll
    for (int t = 0; t < NKT; t++) s += g_partial[(size_t)row*NKT + t];
    g_rowinv[row] = 1.0f / s;
}

// ==================== K4: tensor-core PV (normalize p in place + out = P @ V) ====================
// smem halves: AH [128][72], AL [128][72], BVH [64][72], BVL [64][72]
#define PV_SMEM_BYTES ((9216*2 + 4608*2)*2)

__global__ __launch_bounds__(128) void pv_kernel(float* __restrict__ p, float* __restrict__ out)
{
    extern __shared__ __align__(16) __nv_bfloat16 sm2[];
    __nv_bfloat16* AH  = sm2;
    __nv_bfloat16* AL  = sm2 + 9216;
    __nv_bfloat16* BVH = sm2 + 18432;
    __nv_bfloat16* BVL = sm2 + 23040;
    __shared__ float rs[128];

    const int tid = threadIdx.x, w = tid >> 5, lane = tid & 31;
    const int qt = blockIdx.x, bh = blockIdx.y;
    const int q0 = qt*128;

    {
        const int q = q0 + tid;
        rs[tid] = (q < SEQ) ? g_rowinv[(size_t)bh*SEQ + q] : 0.f;
    }
    __syncthreads();

    float acc[2][8][4];
    #pragma unroll
    for (int a = 0; a < 2; a++)
        #pragma unroll
        for (int b = 0; b < 8; b++)
            #pragma unroll
            for (int c = 0; c < 4; c++) acc[a][b][c] = 0.f;

    const uint32_t aAH = smem_u32(AH), aAL = smem_u32(AL);
    const uint32_t aBH = smem_u32(BVH), aBL = smem_u32(BVL);

    const int half = lane >> 4, l16 = lane & 15;
    const int arow = lane & 15, ak8 = (lane >> 4) * 8;
    const int mi = lane >> 3, l8 = lane & 7;

    for (int c = 0; c < 25; c++) {
        const int s0 = c*64;
        // phase 1a: read e rows (coalesced, 2 rows per iteration), normalize,
        // write p back, split to bf16 hi/lo in smem A
        #pragma unroll 4
        for (int it = 0; it < 16; it++) {
            const int r = w*32 + it*2 + half;
            const int q = q0 + r;
            const bool v = (q < SEQ);
            float* addr = p + ((size_t)bh*SEQ + (v ? q : 0))*SEQ + s0 + l16*4;
            float4 e4 = make_float4(0.f, 0.f, 0.f, 0.f);
            if (v) e4 = *(const float4*)addr;
            const float rv = rs[r];
            e4.x *= rv; e4.y *= rv; e4.z *= rv; e4.w *= rv;
            if (v) *(float4*)addr = e4;
            __nv_bfloat162 h01 = __float22bfloat162_rn(make_float2(e4.x, e4.y));
            __nv_bfloat162 h23 = __float22bfloat162_rn(make_float2(e4.z, e4.w));
            float2 hf01 = __bfloat1622float2(h01), hf23 = __bfloat1622float2(h23);
            __nv_bfloat162 l01 = __float22bfloat162_rn(make_float2(e4.x - hf01.x, e4.y - hf01.y));
            __nv_bfloat162 l23 = __float22bfloat162_rn(make_float2(e4.z - hf23.x, e4.w - hf23.y));
            *(uint2*)&AH[r*72 + l16*4] =
                make_uint2(*(uint32_t*)&h01, *(uint32_t*)&h23);
            *(uint2*)&AL[r*72 + l16*4] =
                make_uint2(*(uint32_t*)&l01, *(uint32_t*)&l23);
        }
        // phase 1b: V tile [64 d][64 s] hi/lo
        #pragma unroll
        for (int j = 0; j < 4; j++) {
            const int idx = tid + j*128;
            const int r = idx >> 3, c8 = idx & 7;
            const size_t src = ((size_t)bh*64 + r)*SEQ + s0 + c8*8;
            *(uint4*)&BVH[r*72 + c8*8] = *(const uint4*)&g_vh[src];
            *(uint4*)&BVL[r*72 + c8*8] = *(const uint4*)&g_vl[src];
        }
        __syncthreads();

        // phase 2: mma
        #pragma unroll
        for (int kc = 0; kc < 4; kc++) {
            uint32_t ah[2][4], al2[2][4], bhf[4][4], blf[4][4];
            #pragma unroll
            for (int mb = 0; mb < 2; mb++) {
                const uint32_t off = (uint32_t)(((w*32 + mb*16 + arow)*72 + kc*16 + ak8) * 2);
                ldsm4(ah[mb],  aAH + off);
                ldsm4(al2[mb], aAL + off);
            }
            #pragma unroll
            for (int nbp = 0; nbp < 4; nbp++) {
                const int n = nbp*16 + (mi >> 1)*8 + l8;
                const uint32_t off = (uint32_t)((n*72 + kc*16 + (mi & 1)*8) * 2);
                ldsm4(bhf[nbp], aBH + off);
                ldsm4(blf[nbp], aBL + off);
            }
            #pragma unroll
            for (int mb = 0; mb < 2; mb++)
                #pragma unroll
                for (int nb = 0; nb < 8; nb++) {
                    const int nbp = nb >> 1, sel = (nb & 1)*2;
                    mma16816(acc[mb][nb], ah[mb],  &bhf[nbp][sel]);
                    mma16816(acc[mb][nb], ah[mb],  &blf[nbp][sel]);
                    mma16816(acc[mb][nb], al2[mb], &bhf[nbp][sel]);
                }
        }
        __syncthreads();
    }

    // epilogue
    const int r0 = lane >> 2, c0 = (lane & 3)*2;
    const int b = bh >> 3, h = bh & 7;
    #pragma unroll
    for (int mb = 0; mb < 2; mb++) {
        const int q1 = q0 + w*32 + mb*16 + r0, q2 = q1 + 8;
        #pragma unroll
        for (int nb = 0; nb < 8; nb++) {
            const int col = h*64 + nb*8 + c0;
            if (q1 < SEQ)
                *(float2*)&out[((size_t)(b*SEQ + q1))*512 + col] =
                    make_float2(acc[mb][nb][0], acc[mb][nb][1]);
            if (q2 < SEQ)
                *(float2*)&out[((size_t)(b*SEQ + q2))*512 + col] =
                    make_float2(acc[mb][nb][2], acc[mb][nb][3]);
        }
    }
}

extern "C" void kernel_launch(void* const* d_in, const int* in_sizes, int n_in,
                              void* d_out, int out_size)
{
    const float* x  = (const float*)d_in[0];
    const float* wq = (const float*)d_in[1];
    const float* bq = (const float*)d_in[2];
    const float* wk = (const float*)d_in[3];
    const float* bk = (const float*)d_in[4];
    const float* wv = (const float*)d_in[5];
    const float* bv = (const float*)d_in[6];
    float* out = (float*)d_out;
    float* p   = out + OUT_ELEMS;

    cudaFuncSetAttribute(score_kernel, cudaFuncAttributeMaxDynamicSharedMemorySize, SC_SMEM_BYTES);
    cudaFuncSetAttribute(pv_kernel,    cudaFuncAttributeMaxDynamicSharedMemorySize, PV_SMEM_BYTES);

    proj_kernel<<<dim3(100, 4, 3), 256>>>(x, wq, bq, wk, bk, wv, bv);
    score_kernel<<<dim3(NKT, 26, BH), 128, SC_SMEM_BYTES>>>(p);
    rowinv_kernel<<<dim3((BH*SEQ + 255)/256), 256>>>();
    pv_kernel<<<dim3(NKT, BH), 128, PV_SMEM_BYTES>>>(p, out);
}